// round 1
// baseline (speedup 1.0000x reference)
#include <cuda_runtime.h>
#include <math.h>

#define HID   2048
#define INTER 8192
#define QKV   8192
#define TV    4096
#define NVH   32
#define KD    128
#define VD    128
#define NKH   16
#define PROJ_ROWS (QKV + TV + 2 * NVH)   // 12352

// ---- scratch (no allocations allowed) ----
__device__ float g_h[HID];
__device__ float g_proj[PROJ_ROWS];
__device__ float g_conv[QKV];
__device__ float g_yg[TV];
__device__ float g_x1[HID];
__device__ float g_hn[HID];
__device__ float g_act[INTER];

__device__ __forceinline__ float warp_sum(float v) {
#pragma unroll
    for (int o = 16; o; o >>= 1) v += __shfl_xor_sync(0xffffffffu, v, o);
    return v;
}

// ---------------- rmsnorm: out = x * rsqrt(mean(x^2)+eps) * (1+w) ----------------
__global__ void rmsnorm_k(const float* __restrict__ x, const float* __restrict__ w,
                          float* __restrict__ out) {
    __shared__ float red[32];
    float s = 0.f;
    for (int i = threadIdx.x; i < HID; i += blockDim.x) {
        float v = x[i];
        s += v * v;
    }
    s = warp_sum(s);
    if ((threadIdx.x & 31) == 0) red[threadIdx.x >> 5] = s;
    __syncthreads();
    if (threadIdx.x < 32) {
        float v = (threadIdx.x < (blockDim.x >> 5)) ? red[threadIdx.x] : 0.f;
        v = warp_sum(v);
        if (threadIdx.x == 0) red[0] = v;
    }
    __syncthreads();
    float inv = rsqrtf(red[0] / (float)HID + 1e-6f);
    for (int i = threadIdx.x; i < HID; i += blockDim.x)
        out[i] = x[i] * inv * (1.f + w[i]);
}

// ---------------- warp-per-row GEMV: out[r] = (add?add[r]:0) + W[r,:]·x ----------------
template <int K, int WPB>
__global__ void gemv_k(const float* __restrict__ W, const float* __restrict__ x,
                       float* __restrict__ out, int rows, const float* __restrict__ add) {
    __shared__ float sx[K];
    for (int i = threadIdx.x; i < K; i += WPB * 32) sx[i] = x[i];
    __syncthreads();
    int warp = threadIdx.x >> 5, lane = threadIdx.x & 31;
    int row = blockIdx.x * WPB + warp;
    if (row >= rows) return;
    const float4* Wr = reinterpret_cast<const float4*>(W + (size_t)row * K);
    const float4* xs = reinterpret_cast<const float4*>(sx);
    float acc = 0.f;
#pragma unroll 4
    for (int j = lane; j < K / 4; j += 32) {
        float4 w4 = __ldg(Wr + j);
        float4 x4 = xs[j];
        acc += w4.x * x4.x + w4.y * x4.y + w4.z * x4.z + w4.w * x4.w;
    }
    acc = warp_sum(acc);
    if (lane == 0) out[row] = (add ? add[row] : 0.f) + acc;
}

// ---------------- fused gate/up GEMV + SwiGLU ----------------
template <int K, int WPB>
__global__ void gateup_k(const float* __restrict__ Wg, const float* __restrict__ Wu,
                         const float* __restrict__ x, float* __restrict__ act, int rows) {
    __shared__ float sx[K];
    for (int i = threadIdx.x; i < K; i += WPB * 32) sx[i] = x[i];
    __syncthreads();
    int warp = threadIdx.x >> 5, lane = threadIdx.x & 31;
    int row = blockIdx.x * WPB + warp;
    if (row >= rows) return;
    const float4* Gr = reinterpret_cast<const float4*>(Wg + (size_t)row * K);
    const float4* Ur = reinterpret_cast<const float4*>(Wu + (size_t)row * K);
    const float4* xs = reinterpret_cast<const float4*>(sx);
    float ag = 0.f, au = 0.f;
#pragma unroll 4
    for (int j = lane; j < K / 4; j += 32) {
        float4 g4 = __ldg(Gr + j);
        float4 u4 = __ldg(Ur + j);
        float4 x4 = xs[j];
        ag += g4.x * x4.x + g4.y * x4.y + g4.z * x4.z + g4.w * x4.w;
        au += u4.x * x4.x + u4.y * x4.y + u4.z * x4.z + u4.w * x4.w;
    }
    ag = warp_sum(ag);
    au = warp_sum(au);
    if (lane == 0) {
        float silu = ag / (1.f + expf(-ag));
        act[row] = silu * au;
    }
}

// ---------------- conv state update + silu ----------------
__global__ void conv_k(const float* __restrict__ cs, const float* __restrict__ cw,
                       const float* __restrict__ proj, float* __restrict__ conv_out,
                       float* __restrict__ out_cs) {
    int i = blockIdx.x * blockDim.x + threadIdx.x;
    if (i >= QKV) return;
    float4 c = __ldg(reinterpret_cast<const float4*>(cs) + i);
    float4 w = __ldg(reinterpret_cast<const float4*>(cw) + i);
    float q = proj[i];
    float s = c.y * w.x + c.z * w.y + c.w * w.z + q * w.w;
    conv_out[i] = s / (1.f + expf(-s));
    reinterpret_cast<float4*>(out_cs)[i] = make_float4(c.y, c.z, c.w, q);
}

// ---------------- gated delta rule: per-head state update ----------------
__global__ void delta_k(const float* __restrict__ S, const float* __restrict__ conv_out,
                        const float* __restrict__ proj, const float* __restrict__ A_log,
                        const float* __restrict__ dt_bias, const float* __restrict__ norm_w,
                        float* __restrict__ Sout, float* __restrict__ yg) {
    __shared__ float sq[KD], sk[KD], red[4];
    int h = blockIdx.x;       // 0..31
    int t = threadIdx.x;      // 0..127
    int kh = h >> 1;          // RATIO = 2

    float qr = conv_out[kh * KD + t];
    float kr = conv_out[NKH * KD + kh * KD + t];
    float v  = conv_out[2 * NKH * KD + h * VD + t];

    // l2 norms of q and k (block reductions over 128 threads)
    float vq = warp_sum(qr * qr);
    float vk = warp_sum(kr * kr);
    if ((t & 31) == 0) { sq[t >> 5] = vq; sk[t >> 5] = vk; }   // reuse heads of sq/sk
    __syncthreads();
    float sumq = sq[0] + sq[1] + sq[2] + sq[3];
    float sumk = sk[0] + sk[1] + sk[2] + sk[3];
    __syncthreads();
    float qn = qr / fmaxf(sqrtf(sumq), 1e-12f);
    float kn = kr / fmaxf(sqrtf(sumk), 1e-12f);
    sq[t] = qn;
    sk[t] = kn;
    __syncthreads();

    float a = proj[QKV + TV + h];
    float b = proj[QKV + TV + NVH + h];
    float beta = 1.f / (1.f + expf(-b));
    float xsp = a + dt_bias[h];
    float sp = (xsp > 20.f) ? xsp : log1pf(expf(xsp));
    float decay = expf(-expf(A_log[h]) * sp);

    const float* Sh = S + (size_t)h * KD * VD;
    float* So = Sout + (size_t)h * KD * VD;

    float Skv = 0.f;
#pragma unroll 8
    for (int kk = 0; kk < KD; kk++) Skv += Sh[kk * VD + t] * sk[kk];
    float dlt = v - Skv;

    float y = 0.f;
#pragma unroll 8
    for (int kk = 0; kk < KD; kk++) {
        float ns = decay * Sh[kk * VD + t] + beta * sk[kk] * dlt;
        So[kk * VD + t] = ns;
        y += ns * sq[kk];
    }

    // rmsnorm of y over VD, * norm_w (NOT 1+w here), then gate with silu(z)
    float vy = warp_sum(y * y);
    if ((t & 31) == 0) red[t >> 5] = vy;
    __syncthreads();
    float sumy = red[0] + red[1] + red[2] + red[3];
    float yn = y * rsqrtf(sumy / (float)VD + 1e-6f) * norm_w[t];
    float z = proj[QKV + h * VD + t];
    yg[h * VD + t] = yn * (z / (1.f + expf(-z)));
}

extern "C" void kernel_launch(void* const* d_in, const int* in_sizes, int n_in,
                              void* d_out, int out_size) {
    const float* x          = (const float*)d_in[0];
    const float* conv_state = (const float*)d_in[1];
    const float* ssm_state  = (const float*)d_in[2];
    const float* in_ln_w    = (const float*)d_in[3];
    const float* in_proj_w  = (const float*)d_in[4];
    const float* conv_w     = (const float*)d_in[5];
    const float* A_log      = (const float*)d_in[6];
    const float* dt_bias    = (const float*)d_in[7];
    const float* norm_w     = (const float*)d_in[8];
    const float* out_proj_w = (const float*)d_in[9];
    const float* post_ln_w  = (const float*)d_in[10];
    const float* gate_w     = (const float*)d_in[11];
    const float* up_w       = (const float*)d_in[12];
    const float* down_w     = (const float*)d_in[13];

    float* out = (float*)d_out;
    float* out_x    = out;                   // [0, 2048)
    float* out_conv = out + HID;             // [2048, 2048+32768)
    float* out_ssm  = out + HID + QKV * 4;   // [34816, 34816+524288)

    float *p_h, *p_proj, *p_conv, *p_yg, *p_x1, *p_hn, *p_act;
    cudaGetSymbolAddress((void**)&p_h,    g_h);
    cudaGetSymbolAddress((void**)&p_proj, g_proj);
    cudaGetSymbolAddress((void**)&p_conv, g_conv);
    cudaGetSymbolAddress((void**)&p_yg,   g_yg);
    cudaGetSymbolAddress((void**)&p_x1,   g_x1);
    cudaGetSymbolAddress((void**)&p_hn,   g_hn);
    cudaGetSymbolAddress((void**)&p_act,  g_act);

    // 1. input rmsnorm
    rmsnorm_k<<<1, 512>>>(x, in_ln_w, p_h);
    // 2. in_proj GEMV: 12352 rows x 2048  (101 MB)
    gemv_k<HID, 8><<<PROJ_ROWS / 8, 256>>>(in_proj_w, p_h, p_proj, PROJ_ROWS, nullptr);
    // 3. conv update + silu; writes new_conv_state to output
    conv_k<<<QKV / 256, 256>>>(conv_state, conv_w, p_proj, p_conv, out_conv);
    // 4. gated delta rule per head; writes new_ssm_state to output
    delta_k<<<NVH, KD>>>(ssm_state, p_conv, p_proj, A_log, dt_bias, norm_w, out_ssm, p_yg);
    // 5. out_proj GEMV + residual: 2048 rows x 4096 (33.5 MB)
    gemv_k<TV, 8><<<HID / 8, 256>>>(out_proj_w, p_yg, p_x1, HID, x);
    // 6. post rmsnorm
    rmsnorm_k<<<1, 512>>>(p_x1, post_ln_w, p_hn);
    // 7. fused gate/up GEMV + SwiGLU: 2x 8192 rows x 2048 (134 MB)
    gateup_k<HID, 8><<<INTER / 8, 256>>>(gate_w, up_w, p_hn, p_act, INTER);
    // 8. down GEMV + residual: 2048 rows x 8192 (67 MB) -> x_out
    gemv_k<INTER, 8><<<HID / 8, 256>>>(down_w, p_act, out_x, HID, p_x1);
}

// round 2
// speedup vs baseline: 1.0638x; 1.0638x over previous
#include <cuda_runtime.h>
#include <math.h>

#define HID   2048
#define INTER 8192
#define QKV   8192
#define TV    4096
#define NVH   32
#define KD    128
#define VD    128
#define NKH   16
#define PROJ_ROWS (QKV + TV + 2 * NVH)   // 12352

// ---- scratch (no allocations allowed) ----
__device__ float g_proj[PROJ_ROWS];
__device__ float g_conv[QKV];
__device__ float g_yg[TV];
__device__ float g_x1[HID];
__device__ float g_act[INTER];

__device__ __forceinline__ float warp_sum(float v) {
#pragma unroll
    for (int o = 16; o; o >>= 1) v += __shfl_xor_sync(0xffffffffu, v, o);
    return v;
}

// ---------------- warp-per-row GEMV, optional fused rmsnorm on the input ----------------
// LN=true: x_used = xin * rsqrt(mean(xin^2)+eps) * (1+lnw)   (computed redundantly per block)
template <int K, int WPB, bool LN>
__global__ void gemv_k(const float* __restrict__ W, const float* __restrict__ xin,
                       const float* __restrict__ lnw,
                       float* __restrict__ out, int rows, const float* __restrict__ add) {
    __shared__ float sx[K];
    __shared__ float sred[WPB + 1];
    if (LN) {
        float s = 0.f;
        for (int i = threadIdx.x; i < K; i += WPB * 32) {
            float v = xin[i];
            sx[i] = v;
            s += v * v;
        }
        s = warp_sum(s);
        if ((threadIdx.x & 31) == 0) sred[threadIdx.x >> 5] = s;
        __syncthreads();
        if (threadIdx.x < 32) {
            float v = (threadIdx.x < WPB) ? sred[threadIdx.x] : 0.f;
            v = warp_sum(v);
            if (threadIdx.x == 0) sred[WPB] = rsqrtf(v / (float)K + 1e-6f);
        }
        __syncthreads();
        float inv = sred[WPB];
        for (int i = threadIdx.x; i < K; i += WPB * 32)
            sx[i] = sx[i] * inv * (1.f + lnw[i]);
        __syncthreads();
    } else {
        for (int i = threadIdx.x; i < K; i += WPB * 32) sx[i] = xin[i];
        __syncthreads();
    }
    int warp = threadIdx.x >> 5, lane = threadIdx.x & 31;
    int row = blockIdx.x * WPB + warp;
    if (row >= rows) return;
    const float4* Wr = reinterpret_cast<const float4*>(W + (size_t)row * K);
    const float4* xs = reinterpret_cast<const float4*>(sx);
    float acc = 0.f;
#pragma unroll 8
    for (int j = lane; j < K / 4; j += 32) {
        float4 w4 = __ldg(Wr + j);
        float4 x4 = xs[j];
        acc += w4.x * x4.x + w4.y * x4.y + w4.z * x4.z + w4.w * x4.w;
    }
    acc = warp_sum(acc);
    if (lane == 0) out[row] = (add ? add[row] : 0.f) + acc;
}

// ---------------- fused gate/up GEMV + SwiGLU, with fused post-rmsnorm ----------------
template <int K, int WPB>
__global__ void gateup_k(const float* __restrict__ Wg, const float* __restrict__ Wu,
                         const float* __restrict__ xin, const float* __restrict__ lnw,
                         float* __restrict__ act, int rows) {
    __shared__ float sx[K];
    __shared__ float sred[WPB + 1];
    {
        float s = 0.f;
        for (int i = threadIdx.x; i < K; i += WPB * 32) {
            float v = xin[i];
            sx[i] = v;
            s += v * v;
        }
        s = warp_sum(s);
        if ((threadIdx.x & 31) == 0) sred[threadIdx.x >> 5] = s;
        __syncthreads();
        if (threadIdx.x < 32) {
            float v = (threadIdx.x < WPB) ? sred[threadIdx.x] : 0.f;
            v = warp_sum(v);
            if (threadIdx.x == 0) sred[WPB] = rsqrtf(v / (float)K + 1e-6f);
        }
        __syncthreads();
        float inv = sred[WPB];
        for (int i = threadIdx.x; i < K; i += WPB * 32)
            sx[i] = sx[i] * inv * (1.f + lnw[i]);
        __syncthreads();
    }
    int warp = threadIdx.x >> 5, lane = threadIdx.x & 31;
    int row = blockIdx.x * WPB + warp;
    if (row >= rows) return;
    const float4* Gr = reinterpret_cast<const float4*>(Wg + (size_t)row * K);
    const float4* Ur = reinterpret_cast<const float4*>(Wu + (size_t)row * K);
    const float4* xs = reinterpret_cast<const float4*>(sx);
    float ag = 0.f, au = 0.f;
#pragma unroll 8
    for (int j = lane; j < K / 4; j += 32) {
        float4 g4 = __ldg(Gr + j);
        float4 u4 = __ldg(Ur + j);
        float4 x4 = xs[j];
        ag += g4.x * x4.x + g4.y * x4.y + g4.z * x4.z + g4.w * x4.w;
        au += u4.x * x4.x + u4.y * x4.y + u4.z * x4.z + u4.w * x4.w;
    }
    ag = warp_sum(ag);
    au = warp_sum(au);
    if (lane == 0) {
        float silu = ag / (1.f + expf(-ag));
        act[row] = silu * au;
    }
}

// ---------------- conv state update + silu ----------------
__global__ void conv_k(const float* __restrict__ cs, const float* __restrict__ cw,
                       const float* __restrict__ proj, float* __restrict__ conv_out,
                       float* __restrict__ out_cs) {
    int i = blockIdx.x * blockDim.x + threadIdx.x;
    if (i >= QKV) return;
    float4 c = __ldg(reinterpret_cast<const float4*>(cs) + i);
    float4 w = __ldg(reinterpret_cast<const float4*>(cw) + i);
    float q = proj[i];
    float s = c.y * w.x + c.z * w.y + c.w * w.z + q * w.w;
    conv_out[i] = s / (1.f + expf(-s));
    reinterpret_cast<float4*>(out_cs)[i] = make_float4(c.y, c.z, c.w, q);
}

// ---------------- gated delta rule, parallel version ----------------
// grid = NVH heads, block = 1024 threads: t = tid&127 (v-column), p = tid>>7 (k-partition of 16)
__global__ void __launch_bounds__(1024, 1)
delta_k(const float* __restrict__ S, const float* __restrict__ conv_out,
        const float* __restrict__ proj, const float* __restrict__ A_log,
        const float* __restrict__ dt_bias, const float* __restrict__ norm_w,
        float* __restrict__ Sout, float* __restrict__ yg) {
    __shared__ float sq[KD], sk[KD], sdelta[VD], sred[8];
    __shared__ float spart[8][VD];
    int h = blockIdx.x;
    int tid = threadIdx.x;
    int t = tid & (VD - 1);
    int p = tid >> 7;          // 0..7, each handles 16 consecutive k's
    int kh = h >> 1;           // RATIO = 2

    if (tid < KD) {
        float qr = conv_out[kh * KD + tid];
        float kr = conv_out[NKH * KD + kh * KD + tid];
        sq[tid] = qr;
        sk[tid] = kr;
        float vq = warp_sum(qr * qr);
        float vk = warp_sum(kr * kr);
        if ((tid & 31) == 0) { sred[tid >> 5] = vq; sred[4 + (tid >> 5)] = vk; }
    }
    __syncthreads();
    float sumq = sred[0] + sred[1] + sred[2] + sred[3];
    float sumk = sred[4] + sred[5] + sred[6] + sred[7];
    float inq = 1.f / fmaxf(sqrtf(sumq), 1e-12f);
    float ink = 1.f / fmaxf(sqrtf(sumk), 1e-12f);

    float a = proj[QKV + TV + h];
    float b = proj[QKV + TV + NVH + h];
    float beta = 1.f / (1.f + expf(-b));
    float xsp = a + dt_bias[h];
    float sp = (xsp > 20.f) ? xsp : log1pf(expf(xsp));
    float decay = expf(-expf(A_log[h]) * sp);

    const float* Sh = S + (size_t)h * KD * VD;
    float* So = Sout + (size_t)h * KD * VD;

    // phase 1: load 16 state elements into registers, partial Sk dot
    float Sreg[16];
    float acc = 0.f;
#pragma unroll
    for (int j = 0; j < 16; j++) {
        int k = p * 16 + j;
        Sreg[j] = Sh[k * VD + t];
        acc += Sreg[j] * sk[k];
    }
    spart[p][t] = acc * ink;
    __syncthreads();
    if (p == 0) {
        float v = conv_out[2 * NKH * KD + h * VD + t];
        float s = 0.f;
#pragma unroll
        for (int j = 0; j < 8; j++) s += spart[j][t];
        sdelta[t] = v - s;
    }
    __syncthreads();

    // phase 2: state update + partial y
    float d = sdelta[t];
    float yacc = 0.f;
#pragma unroll
    for (int j = 0; j < 16; j++) {
        int k = p * 16 + j;
        float ns = decay * Sreg[j] + beta * (sk[k] * ink) * d;
        So[k * VD + t] = ns;
        yacc += ns * sq[k];
    }
    spart[p][t] = yacc * inq;
    __syncthreads();

    // finish: reduce y over partitions, rmsnorm * norm_w, gate with silu(z)
    float y = 0.f;
    if (tid < VD) {
#pragma unroll
        for (int j = 0; j < 8; j++) y += spart[j][tid];
        float vy = warp_sum(y * y);
        if ((tid & 31) == 0) sred[tid >> 5] = vy;
    }
    __syncthreads();
    if (tid < VD) {
        float sumy = sred[0] + sred[1] + sred[2] + sred[3];
        float yn = y * rsqrtf(sumy / (float)VD + 1e-6f) * norm_w[tid];
        float z = proj[QKV + h * VD + tid];
        yg[h * VD + tid] = yn * (z / (1.f + expf(-z)));
    }
}

extern "C" void kernel_launch(void* const* d_in, const int* in_sizes, int n_in,
                              void* d_out, int out_size) {
    const float* x          = (const float*)d_in[0];
    const float* conv_state = (const float*)d_in[1];
    const float* ssm_state  = (const float*)d_in[2];
    const float* in_ln_w    = (const float*)d_in[3];
    const float* in_proj_w  = (const float*)d_in[4];
    const float* conv_w     = (const float*)d_in[5];
    const float* A_log      = (const float*)d_in[6];
    const float* dt_bias    = (const float*)d_in[7];
    const float* norm_w     = (const float*)d_in[8];
    const float* out_proj_w = (const float*)d_in[9];
    const float* post_ln_w  = (const float*)d_in[10];
    const float* gate_w     = (const float*)d_in[11];
    const float* up_w       = (const float*)d_in[12];
    const float* down_w     = (const float*)d_in[13];

    float* out = (float*)d_out;
    float* out_x    = out;                   // [0, 2048)
    float* out_conv = out + HID;             // new_conv_state (QKV x 4)
    float* out_ssm  = out + HID + QKV * 4;   // new_ssm_state (32 x 128 x 128)

    float *p_proj, *p_conv, *p_yg, *p_x1, *p_act;
    cudaGetSymbolAddress((void**)&p_proj, g_proj);
    cudaGetSymbolAddress((void**)&p_conv, g_conv);
    cudaGetSymbolAddress((void**)&p_yg,   g_yg);
    cudaGetSymbolAddress((void**)&p_x1,   g_x1);
    cudaGetSymbolAddress((void**)&p_act,  g_act);

    // 1. in_proj GEMV with fused input rmsnorm: 12352 x 2048 (101 MB)
    gemv_k<HID, 8, true><<<PROJ_ROWS / 8, 256>>>(in_proj_w, x, in_ln_w, p_proj, PROJ_ROWS, nullptr);
    // 2. conv update + silu; writes new_conv_state to output
    conv_k<<<QKV / 256, 256>>>(conv_state, conv_w, p_proj, p_conv, out_conv);
    // 3. gated delta rule per head; writes new_ssm_state to output
    delta_k<<<NVH, 1024>>>(ssm_state, p_conv, p_proj, A_log, dt_bias, norm_w, out_ssm, p_yg);
    // 4. out_proj GEMV + residual: 2048 x 4096 (33.5 MB)
    gemv_k<TV, 8, false><<<HID / 8, 256>>>(out_proj_w, p_yg, nullptr, p_x1, HID, x);
    // 5. fused post-rmsnorm + gate/up GEMV + SwiGLU: 2x 8192 x 2048 (134 MB)
    gateup_k<HID, 8><<<INTER / 8, 256>>>(gate_w, up_w, p_x1, post_ln_w, p_act, INTER);
    // 6. down GEMV + residual: 2048 x 8192 (67 MB) -> x_out
    gemv_k<INTER, 8, false><<<HID / 8, 256>>>(down_w, p_act, nullptr, out_x, HID, p_x1);
}

// round 3
// speedup vs baseline: 1.0873x; 1.0221x over previous
#include <cuda_runtime.h>
#include <math.h>

#define HID   2048
#define INTER 8192
#define QKV   8192
#define TV    4096
#define NVH   32
#define KD    128
#define VD    128
#define NKH   16
#define PROJ_ROWS (QKV + TV + 2 * NVH)   // 12352

// ---- scratch ----
__device__ float g_proj[PROJ_ROWS];
__device__ float g_conv[QKV];
__device__ float g_yg[TV];
__device__ float g_x1[HID];
__device__ float g_act[INTER];

__device__ __forceinline__ float warp_sum(float v) {
#pragma unroll
    for (int o = 16; o; o >>= 1) v += __shfl_xor_sync(0xffffffffu, v, o);
    return v;
}

// ---------------- warp-per-row GEMV with fused input rmsnorm ----------------
template <int K, int WPB, bool LN>
__global__ void gemv_k(const float* __restrict__ W, const float* __restrict__ xin,
                       const float* __restrict__ lnw,
                       float* __restrict__ out, int rows) {
    __shared__ float sx[K];
    __shared__ float sred[WPB + 1];
    if (LN) {
        float s = 0.f;
        for (int i = threadIdx.x; i < K; i += WPB * 32) {
            float v = xin[i];
            sx[i] = v;
            s += v * v;
        }
        s = warp_sum(s);
        if ((threadIdx.x & 31) == 0) sred[threadIdx.x >> 5] = s;
        __syncthreads();
        if (threadIdx.x < 32) {
            float v = (threadIdx.x < WPB) ? sred[threadIdx.x] : 0.f;
            v = warp_sum(v);
            if (threadIdx.x == 0) sred[WPB] = rsqrtf(v / (float)K + 1e-6f);
        }
        __syncthreads();
        float inv = sred[WPB];
        for (int i = threadIdx.x; i < K; i += WPB * 32)
            sx[i] = sx[i] * inv * (1.f + lnw[i]);
        __syncthreads();
    } else {
        for (int i = threadIdx.x; i < K; i += WPB * 32) sx[i] = xin[i];
        __syncthreads();
    }
    int warp = threadIdx.x >> 5, lane = threadIdx.x & 31;
    int row = blockIdx.x * WPB + warp;
    if (row >= rows) return;
    const float4* Wr = reinterpret_cast<const float4*>(W + (size_t)row * K);
    const float4* xs = reinterpret_cast<const float4*>(sx);
    float acc = 0.f;
#pragma unroll
    for (int j = 0; j < K / 128; j++) {
        float4 w4 = __ldg(Wr + j * 32 + lane);
        float4 x4 = xs[j * 32 + lane];
        acc += w4.x * x4.x + w4.y * x4.y + w4.z * x4.z + w4.w * x4.w;
    }
    acc = warp_sum(acc);
    if (lane == 0) out[row] = acc;
}

// ---------------- split-K warp-per-row GEMV, atomicAdd into pre-initialized out ----------------
template <int K, int SPLIT, int WPB>
__global__ void gemv_split_k(const float* __restrict__ W, const float* __restrict__ x,
                             float* __restrict__ out, int rows) {
    constexpr int KC = K / SPLIT;
    __shared__ float sx[KC];
    const int chunk = blockIdx.y;
    const float* xc = x + chunk * KC;
    for (int i = threadIdx.x; i < KC; i += WPB * 32) sx[i] = xc[i];
    __syncthreads();
    int warp = threadIdx.x >> 5, lane = threadIdx.x & 31;
    int row = blockIdx.x * WPB + warp;
    if (row >= rows) return;
    const float4* Wr = reinterpret_cast<const float4*>(W + (size_t)row * K + chunk * KC);
    const float4* xs = reinterpret_cast<const float4*>(sx);
    float acc = 0.f;
#pragma unroll
    for (int j = 0; j < KC / 128; j++) {
        float4 w4 = __ldg(Wr + j * 32 + lane);
        float4 x4 = xs[j * 32 + lane];
        acc += w4.x * x4.x + w4.y * x4.y + w4.z * x4.z + w4.w * x4.w;
    }
    acc = warp_sum(acc);
    if (lane == 0) atomicAdd(&out[row], acc);
}

// ---------------- fused post-rmsnorm + gate/up GEMV + SwiGLU (+ copies x1 -> out_x) ----------------
template <int K, int WPB>
__global__ void gateup_k(const float* __restrict__ Wg, const float* __restrict__ Wu,
                         const float* __restrict__ xin, const float* __restrict__ lnw,
                         float* __restrict__ act, float* __restrict__ xcopy, int rows) {
    __shared__ float sx[K];
    __shared__ float sred[WPB + 1];
    {
        float s = 0.f;
        bool cp = (blockIdx.x == 0);
        for (int i = threadIdx.x; i < K; i += WPB * 32) {
            float v = xin[i];
            sx[i] = v;
            if (cp) xcopy[i] = v;   // seed residual for the down-proj atomics
            s += v * v;
        }
        s = warp_sum(s);
        if ((threadIdx.x & 31) == 0) sred[threadIdx.x >> 5] = s;
        __syncthreads();
        if (threadIdx.x < 32) {
            float v = (threadIdx.x < WPB) ? sred[threadIdx.x] : 0.f;
            v = warp_sum(v);
            if (threadIdx.x == 0) sred[WPB] = rsqrtf(v / (float)K + 1e-6f);
        }
        __syncthreads();
        float inv = sred[WPB];
        for (int i = threadIdx.x; i < K; i += WPB * 32)
            sx[i] = sx[i] * inv * (1.f + lnw[i]);
        __syncthreads();
    }
    int warp = threadIdx.x >> 5, lane = threadIdx.x & 31;
    int row = blockIdx.x * WPB + warp;
    if (row >= rows) return;
    const float4* Gr = reinterpret_cast<const float4*>(Wg + (size_t)row * K);
    const float4* Ur = reinterpret_cast<const float4*>(Wu + (size_t)row * K);
    const float4* xs = reinterpret_cast<const float4*>(sx);
    float ag = 0.f, au = 0.f;
#pragma unroll
    for (int j = 0; j < K / 128; j++) {
        float4 g4 = __ldg(Gr + j * 32 + lane);
        float4 u4 = __ldg(Ur + j * 32 + lane);
        float4 x4 = xs[j * 32 + lane];
        ag += g4.x * x4.x + g4.y * x4.y + g4.z * x4.z + g4.w * x4.w;
        au += u4.x * x4.x + u4.y * x4.y + u4.z * x4.z + u4.w * x4.w;
    }
    ag = warp_sum(ag);
    au = warp_sum(au);
    if (lane == 0) {
        float silu = ag / (1.f + expf(-ag));
        act[row] = silu * au;
    }
}

// ---------------- conv state update + silu; also seeds x1 = x (residual base) ----------------
__global__ void conv_k(const float* __restrict__ cs, const float* __restrict__ cw,
                       const float* __restrict__ proj, const float* __restrict__ x,
                       float* __restrict__ conv_out, float* __restrict__ out_cs,
                       float* __restrict__ x1) {
    int i = blockIdx.x * blockDim.x + threadIdx.x;
    if (i >= QKV) return;
    if (i < HID) x1[i] = x[i];
    float4 c = __ldg(reinterpret_cast<const float4*>(cs) + i);
    float4 w = __ldg(reinterpret_cast<const float4*>(cw) + i);
    float q = proj[i];
    float s = c.y * w.x + c.z * w.y + c.w * w.z + q * w.w;
    conv_out[i] = s / (1.f + expf(-s));
    reinterpret_cast<float4*>(out_cs)[i] = make_float4(c.y, c.z, c.w, q);
}

// ---------------- gated delta rule, parallel ----------------
__global__ void __launch_bounds__(1024, 1)
delta_k(const float* __restrict__ S, const float* __restrict__ conv_out,
        const float* __restrict__ proj, const float* __restrict__ A_log,
        const float* __restrict__ dt_bias, const float* __restrict__ norm_w,
        float* __restrict__ Sout, float* __restrict__ yg) {
    __shared__ float sq[KD], sk[KD], sdelta[VD], sred[8];
    __shared__ float spart[8][VD];
    int h = blockIdx.x;
    int tid = threadIdx.x;
    int t = tid & (VD - 1);
    int p = tid >> 7;
    int kh = h >> 1;

    if (tid < KD) {
        float qr = conv_out[kh * KD + tid];
        float kr = conv_out[NKH * KD + kh * KD + tid];
        sq[tid] = qr;
        sk[tid] = kr;
        float vq = warp_sum(qr * qr);
        float vk = warp_sum(kr * kr);
        if ((tid & 31) == 0) { sred[tid >> 5] = vq; sred[4 + (tid >> 5)] = vk; }
    }
    __syncthreads();
    float sumq = sred[0] + sred[1] + sred[2] + sred[3];
    float sumk = sred[4] + sred[5] + sred[6] + sred[7];
    float inq = 1.f / fmaxf(sqrtf(sumq), 1e-12f);
    float ink = 1.f / fmaxf(sqrtf(sumk), 1e-12f);

    float a = proj[QKV + TV + h];
    float b = proj[QKV + TV + NVH + h];
    float beta = 1.f / (1.f + expf(-b));
    float xsp = a + dt_bias[h];
    float sp = (xsp > 20.f) ? xsp : log1pf(expf(xsp));
    float decay = expf(-expf(A_log[h]) * sp);

    const float* Sh = S + (size_t)h * KD * VD;
    float* So = Sout + (size_t)h * KD * VD;

    float Sreg[16];
    float acc = 0.f;
#pragma unroll
    for (int j = 0; j < 16; j++) {
        int k = p * 16 + j;
        Sreg[j] = Sh[k * VD + t];
        acc += Sreg[j] * sk[k];
    }
    spart[p][t] = acc * ink;
    __syncthreads();
    if (p == 0) {
        float v = conv_out[2 * NKH * KD + h * VD + t];
        float s = 0.f;
#pragma unroll
        for (int j = 0; j < 8; j++) s += spart[j][t];
        sdelta[t] = v - s;
    }
    __syncthreads();

    float d = sdelta[t];
    float yacc = 0.f;
#pragma unroll
    for (int j = 0; j < 16; j++) {
        int k = p * 16 + j;
        float ns = decay * Sreg[j] + beta * (sk[k] * ink) * d;
        So[k * VD + t] = ns;
        yacc += ns * sq[k];
    }
    spart[p][t] = yacc * inq;
    __syncthreads();

    float y = 0.f;
    if (tid < VD) {
#pragma unroll
        for (int j = 0; j < 8; j++) y += spart[j][tid];
        float vy = warp_sum(y * y);
        if ((tid & 31) == 0) sred[tid >> 5] = vy;
    }
    __syncthreads();
    if (tid < VD) {
        float sumy = sred[0] + sred[1] + sred[2] + sred[3];
        float yn = y * rsqrtf(sumy / (float)VD + 1e-6f) * norm_w[tid];
        float z = proj[QKV + h * VD + tid];
        yg[h * VD + tid] = yn * (z / (1.f + expf(-z)));
    }
}

extern "C" void kernel_launch(void* const* d_in, const int* in_sizes, int n_in,
                              void* d_out, int out_size) {
    const float* x          = (const float*)d_in[0];
    const float* conv_state = (const float*)d_in[1];
    const float* ssm_state  = (const float*)d_in[2];
    const float* in_ln_w    = (const float*)d_in[3];
    const float* in_proj_w  = (const float*)d_in[4];
    const float* conv_w     = (const float*)d_in[5];
    const float* A_log      = (const float*)d_in[6];
    const float* dt_bias    = (const float*)d_in[7];
    const float* norm_w     = (const float*)d_in[8];
    const float* out_proj_w = (const float*)d_in[9];
    const float* post_ln_w  = (const float*)d_in[10];
    const float* gate_w     = (const float*)d_in[11];
    const float* up_w       = (const float*)d_in[12];
    const float* down_w     = (const float*)d_in[13];

    float* out = (float*)d_out;
    float* out_x    = out;
    float* out_conv = out + HID;
    float* out_ssm  = out + HID + QKV * 4;

    float *p_proj, *p_conv, *p_yg, *p_x1, *p_act;
    cudaGetSymbolAddress((void**)&p_proj, g_proj);
    cudaGetSymbolAddress((void**)&p_conv, g_conv);
    cudaGetSymbolAddress((void**)&p_yg,   g_yg);
    cudaGetSymbolAddress((void**)&p_x1,   g_x1);
    cudaGetSymbolAddress((void**)&p_act,  g_act);

    // 1. in_proj GEMV with fused input rmsnorm: 12352 x 2048 (101 MB)
    gemv_k<HID, 8, true><<<PROJ_ROWS / 8, 256>>>(in_proj_w, x, in_ln_w, p_proj, PROJ_ROWS);
    // 2. conv update + silu; writes new_conv_state; seeds x1 = x
    conv_k<<<QKV / 256, 256>>>(conv_state, conv_w, p_proj, x, p_conv, out_conv, p_x1);
    // 3. gated delta rule; writes new_ssm_state
    delta_k<<<NVH, 1024>>>(ssm_state, p_conv, p_proj, A_log, dt_bias, norm_w, out_ssm, p_yg);
    // 4. out_proj split-K GEMV, accumulates onto x1 (= x residual): 2048 x 4096 (33.5 MB)
    gemv_split_k<TV, 4, 8><<<dim3(HID / 8, 4), 256>>>(out_proj_w, p_yg, p_x1, HID);
    // 5. fused post-rmsnorm + gate/up GEMV + SwiGLU; block 0 seeds out_x = x1
    gateup_k<HID, 8><<<INTER / 8, 256>>>(gate_w, up_w, p_x1, post_ln_w, p_act, out_x, INTER);
    // 6. down split-K GEMV, accumulates onto out_x (= x1 residual): 2048 x 8192 (67 MB)
    gemv_split_k<INTER, 4, 8><<<dim3(HID / 8, 4), 256>>>(down_w, p_act, out_x, HID);
}

// round 4
// speedup vs baseline: 1.1026x; 1.0141x over previous
#include <cuda_runtime.h>
#include <math.h>

#define HID   2048
#define INTER 8192
#define QKV   8192
#define TV    4096
#define NVH   32
#define KD    128
#define VD    128
#define NKH   16
#define PROJ_ROWS (QKV + TV + 2 * NVH)   // 12352

// ---- scratch ----
__device__ float g_proj[PROJ_ROWS];
__device__ float g_yg[TV];
__device__ float g_x1[HID];
__device__ float g_act[INTER];

__device__ __forceinline__ float warp_sum(float v) {
#pragma unroll
    for (int o = 16; o; o >>= 1) v += __shfl_xor_sync(0xffffffffu, v, o);
    return v;
}

// ---------------- warp-per-row GEMV, register-batched loads, optional fused rmsnorm ----------------
// Also: block 0 seeds xcopy = xin (raw) when xcopy != nullptr.
template <int K, int WPB, bool LN>
__global__ void __launch_bounds__(WPB * 32)
gemv_k(const float* __restrict__ W, const float* __restrict__ xin,
       const float* __restrict__ lnw, float* __restrict__ out, int rows,
       float* __restrict__ xcopy) {
    __shared__ float sx[K];
    __shared__ float sred[WPB + 1];
    if (LN) {
        float s = 0.f;
        bool cp = (xcopy != nullptr) && (blockIdx.x == 0);
        for (int i = threadIdx.x; i < K; i += WPB * 32) {
            float v = xin[i];
            sx[i] = v;
            if (cp) xcopy[i] = v;
            s += v * v;
        }
        s = warp_sum(s);
        if ((threadIdx.x & 31) == 0) sred[threadIdx.x >> 5] = s;
        __syncthreads();
        if (threadIdx.x < 32) {
            float v = (threadIdx.x < WPB) ? sred[threadIdx.x] : 0.f;
            v = warp_sum(v);
            if (threadIdx.x == 0) sred[WPB] = rsqrtf(v / (float)K + 1e-6f);
        }
        __syncthreads();
        float inv = sred[WPB];
        for (int i = threadIdx.x; i < K; i += WPB * 32)
            sx[i] = sx[i] * inv * (1.f + lnw[i]);
        __syncthreads();
    } else {
        for (int i = threadIdx.x; i < K; i += WPB * 32) sx[i] = xin[i];
        __syncthreads();
    }
    int warp = threadIdx.x >> 5, lane = threadIdx.x & 31;
    int row = blockIdx.x * WPB + warp;
    if (row >= rows) return;
    const float4* Wr = reinterpret_cast<const float4*>(W + (size_t)row * K);
    const float4* xs = reinterpret_cast<const float4*>(sx);
    constexpr int NL = K / 128;          // float4 loads per lane (16 for K=2048)
    float4 wb[NL];
#pragma unroll
    for (int j = 0; j < NL; j++) wb[j] = __ldg(Wr + j * 32 + lane);
    float acc = 0.f;
#pragma unroll
    for (int j = 0; j < NL; j++) {
        float4 x4 = xs[j * 32 + lane];
        acc += wb[j].x * x4.x + wb[j].y * x4.y + wb[j].z * x4.z + wb[j].w * x4.w;
    }
    acc = warp_sum(acc);
    if (lane == 0) out[row] = acc;
}

// ---------------- split-K warp-per-row GEMV, register-batched, atomicAdd into out ----------------
template <int K, int SPLIT, int WPB>
__global__ void __launch_bounds__(WPB * 32)
gemv_split_k(const float* __restrict__ W, const float* __restrict__ x,
             float* __restrict__ out, int rows) {
    constexpr int KC = K / SPLIT;
    __shared__ float sx[KC];
    const int chunk = blockIdx.y;
    const float* xc = x + chunk * KC;
    for (int i = threadIdx.x; i < KC; i += WPB * 32) sx[i] = xc[i];
    __syncthreads();
    int warp = threadIdx.x >> 5, lane = threadIdx.x & 31;
    int row = blockIdx.x * WPB + warp;
    if (row >= rows) return;
    const float4* Wr = reinterpret_cast<const float4*>(W + (size_t)row * K + chunk * KC);
    const float4* xs = reinterpret_cast<const float4*>(sx);
    constexpr int NL = KC / 128;
    float4 wb[NL];
#pragma unroll
    for (int j = 0; j < NL; j++) wb[j] = __ldg(Wr + j * 32 + lane);
    float acc = 0.f;
#pragma unroll
    for (int j = 0; j < NL; j++) {
        float4 x4 = xs[j * 32 + lane];
        acc += wb[j].x * x4.x + wb[j].y * x4.y + wb[j].z * x4.z + wb[j].w * x4.w;
    }
    acc = warp_sum(acc);
    if (lane == 0) atomicAdd(&out[row], acc);
}

// ---------------- fused post-rmsnorm + gate/up GEMV + SwiGLU (+ seeds out_x = x1) ----------------
template <int K, int WPB>
__global__ void __launch_bounds__(WPB * 32)
gateup_k(const float* __restrict__ Wg, const float* __restrict__ Wu,
         const float* __restrict__ xin, const float* __restrict__ lnw,
         float* __restrict__ act, float* __restrict__ xcopy, int rows) {
    __shared__ float sx[K];
    __shared__ float sred[WPB + 1];
    {
        float s = 0.f;
        bool cp = (blockIdx.x == 0);
        for (int i = threadIdx.x; i < K; i += WPB * 32) {
            float v = xin[i];
            sx[i] = v;
            if (cp) xcopy[i] = v;
            s += v * v;
        }
        s = warp_sum(s);
        if ((threadIdx.x & 31) == 0) sred[threadIdx.x >> 5] = s;
        __syncthreads();
        if (threadIdx.x < 32) {
            float v = (threadIdx.x < WPB) ? sred[threadIdx.x] : 0.f;
            v = warp_sum(v);
            if (threadIdx.x == 0) sred[WPB] = rsqrtf(v / (float)K + 1e-6f);
        }
        __syncthreads();
        float inv = sred[WPB];
        for (int i = threadIdx.x; i < K; i += WPB * 32)
            sx[i] = sx[i] * inv * (1.f + lnw[i]);
        __syncthreads();
    }
    int warp = threadIdx.x >> 5, lane = threadIdx.x & 31;
    int row = blockIdx.x * WPB + warp;
    if (row >= rows) return;
    const float4* Gr = reinterpret_cast<const float4*>(Wg + (size_t)row * K);
    const float4* Ur = reinterpret_cast<const float4*>(Wu + (size_t)row * K);
    const float4* xs = reinterpret_cast<const float4*>(sx);
    constexpr int NL = K / 128;          // 16
    float ag = 0.f, au = 0.f;
#pragma unroll
    for (int c = 0; c < 2; c++) {
        float4 gb[NL / 2], ub[NL / 2];
#pragma unroll
        for (int j = 0; j < NL / 2; j++) {
            gb[j] = __ldg(Gr + c * (NL / 2) * 32 + j * 32 + lane);
            ub[j] = __ldg(Ur + c * (NL / 2) * 32 + j * 32 + lane);
        }
#pragma unroll
        for (int j = 0; j < NL / 2; j++) {
            float4 x4 = xs[c * (NL / 2) * 32 + j * 32 + lane];
            ag += gb[j].x * x4.x + gb[j].y * x4.y + gb[j].z * x4.z + gb[j].w * x4.w;
            au += ub[j].x * x4.x + ub[j].y * x4.y + ub[j].z * x4.z + ub[j].w * x4.w;
        }
    }
    ag = warp_sum(ag);
    au = warp_sum(au);
    if (lane == 0) {
        float silu = ag / (1.f + expf(-ag));
        act[row] = silu * au;
    }
}

// ---------------- gated delta rule with fused conv update ----------------
// grid = NVH heads, 1024 threads. Computes silu-conv for the q/k/v rows this head
// consumes, writes its slice of new_conv_state (q/k slices: even heads only),
// then does the delta-rule state update + y norm/gating.
__global__ void __launch_bounds__(1024, 1)
delta_k(const float* __restrict__ S, const float* __restrict__ proj,
        const float* __restrict__ cs, const float* __restrict__ cw,
        const float* __restrict__ A_log, const float* __restrict__ dt_bias,
        const float* __restrict__ norm_w,
        float* __restrict__ Sout, float* __restrict__ out_cs, float* __restrict__ yg) {
    __shared__ float sq[KD], sk[KD], sv[VD], sdelta[VD], sred[8];
    __shared__ float spart[8][VD];
    int h = blockIdx.x;
    int tid = threadIdx.x;
    int t = tid & (VD - 1);
    int p = tid >> 7;
    int kh = h >> 1;

    // fused conv for the 384 rows this head needs
    if (tid < 384) {
        int row;
        if (tid < 128)      row = kh * KD + tid;
        else if (tid < 256) row = NKH * KD + kh * KD + (tid - 128);
        else                row = 2 * NKH * KD + h * VD + (tid - 256);
        float4 c = __ldg(reinterpret_cast<const float4*>(cs) + row);
        float4 w = __ldg(reinterpret_cast<const float4*>(cw) + row);
        float q = proj[row];
        float s = c.y * w.x + c.z * w.y + c.w * w.z + q * w.w;
        float act = s / (1.f + expf(-s));
        if (tid < 128)      sq[tid] = act;
        else if (tid < 256) sk[tid - 128] = act;
        else                sv[tid - 256] = act;
        if (tid >= 256 || (h & 1) == 0)
            reinterpret_cast<float4*>(out_cs)[row] = make_float4(c.y, c.z, c.w, q);
    }
    __syncthreads();

    // l2 norms of q and k
    if (tid < 256) {
        float v = (tid < 128) ? sq[tid] : sk[tid - 128];
        float ss = warp_sum(v * v);
        if ((tid & 31) == 0) sred[tid >> 5] = ss;   // 0-3: q, 4-7: k
    }
    __syncthreads();
    float sumq = sred[0] + sred[1] + sred[2] + sred[3];
    float sumk = sred[4] + sred[5] + sred[6] + sred[7];
    float inq = 1.f / fmaxf(sqrtf(sumq), 1e-12f);
    float ink = 1.f / fmaxf(sqrtf(sumk), 1e-12f);

    float a = proj[QKV + TV + h];
    float b = proj[QKV + TV + NVH + h];
    float beta = 1.f / (1.f + expf(-b));
    float xsp = a + dt_bias[h];
    float sp = (xsp > 20.f) ? xsp : log1pf(expf(xsp));
    float decay = expf(-expf(A_log[h]) * sp);

    const float* Sh = S + (size_t)h * KD * VD;
    float* So = Sout + (size_t)h * KD * VD;

    // phase 1: 16 state rows per partition, partial Sk dot
    float Sreg[16];
    float acc = 0.f;
#pragma unroll
    for (int j = 0; j < 16; j++) {
        int k = p * 16 + j;
        Sreg[j] = Sh[k * VD + t];
        acc += Sreg[j] * sk[k];
    }
    spart[p][t] = acc * ink;
    __syncthreads();
    if (p == 0) {
        float s = 0.f;
#pragma unroll
        for (int j = 0; j < 8; j++) s += spart[j][t];
        sdelta[t] = sv[t] - s;
    }
    __syncthreads();

    // phase 2: state update + partial y
    float d = sdelta[t];
    float yacc = 0.f;
#pragma unroll
    for (int j = 0; j < 16; j++) {
        int k = p * 16 + j;
        float ns = decay * Sreg[j] + beta * (sk[k] * ink) * d;
        So[k * VD + t] = ns;
        yacc += ns * sq[k];
    }
    spart[p][t] = yacc * inq;
    __syncthreads();

    // finish: reduce y, rmsnorm * norm_w, gate with silu(z)
    float y = 0.f;
    if (tid < VD) {
#pragma unroll
        for (int j = 0; j < 8; j++) y += spart[j][tid];
        float vy = warp_sum(y * y);
        if ((tid & 31) == 0) sred[tid >> 5] = vy;
    }
    __syncthreads();
    if (tid < VD) {
        float sumy = sred[0] + sred[1] + sred[2] + sred[3];
        float yn = y * rsqrtf(sumy / (float)VD + 1e-6f) * norm_w[tid];
        float z = proj[QKV + h * VD + tid];
        yg[h * VD + tid] = yn * (z / (1.f + expf(-z)));
    }
}

extern "C" void kernel_launch(void* const* d_in, const int* in_sizes, int n_in,
                              void* d_out, int out_size) {
    const float* x          = (const float*)d_in[0];
    const float* conv_state = (const float*)d_in[1];
    const float* ssm_state  = (const float*)d_in[2];
    const float* in_ln_w    = (const float*)d_in[3];
    const float* in_proj_w  = (const float*)d_in[4];
    const float* conv_w     = (const float*)d_in[5];
    const float* A_log      = (const float*)d_in[6];
    const float* dt_bias    = (const float*)d_in[7];
    const float* norm_w     = (const float*)d_in[8];
    const float* out_proj_w = (const float*)d_in[9];
    const float* post_ln_w  = (const float*)d_in[10];
    const float* gate_w     = (const float*)d_in[11];
    const float* up_w       = (const float*)d_in[12];
    const float* down_w     = (const float*)d_in[13];

    float* out = (float*)d_out;
    float* out_x    = out;
    float* out_conv = out + HID;
    float* out_ssm  = out + HID + QKV * 4;

    float *p_proj, *p_yg, *p_x1, *p_act;
    cudaGetSymbolAddress((void**)&p_proj, g_proj);
    cudaGetSymbolAddress((void**)&p_yg,   g_yg);
    cudaGetSymbolAddress((void**)&p_x1,   g_x1);
    cudaGetSymbolAddress((void**)&p_act,  g_act);

    // 1. in_proj GEMV with fused input rmsnorm (block 0 seeds x1 = x): 12352 x 2048
    gemv_k<HID, 8, true><<<PROJ_ROWS / 8, 256>>>(in_proj_w, x, in_ln_w, p_proj, PROJ_ROWS, p_x1);
    // 2. gated delta rule + fused conv; writes new_conv_state and new_ssm_state
    delta_k<<<NVH, 1024>>>(ssm_state, p_proj, conv_state, conv_w,
                           A_log, dt_bias, norm_w, out_ssm, out_conv, p_yg);
    // 3. out_proj split-K GEMV, accumulates onto x1: 2048 x 4096
    gemv_split_k<TV, 2, 8><<<dim3(HID / 8, 2), 256>>>(out_proj_w, p_yg, p_x1, HID);
    // 4. fused post-rmsnorm + gate/up GEMV + SwiGLU; block 0 seeds out_x = x1
    gateup_k<HID, 8><<<INTER / 8, 256>>>(gate_w, up_w, p_x1, post_ln_w, p_act, out_x, INTER);
    // 5. down split-K GEMV, accumulates onto out_x: 2048 x 8192
    gemv_split_k<INTER, 4, 8><<<dim3(HID / 8, 4), 256>>>(down_w, p_act, out_x, HID);
}

// round 6
// speedup vs baseline: 1.2078x; 1.0954x over previous
#include <cuda_runtime.h>
#include <math.h>
#include <cstdint>

#define HID   2048
#define INTER 8192
#define QKV   8192
#define TV    4096
#define NVH   32
#define KD    128
#define VD    128
#define NKH   16
#define PROJ_ROWS (QKV + TV + 2 * NVH)   // 12352

#define MODE_PLAIN  0
#define MODE_ATOMIC 1
#define MODE_GATEUP 2

// ---- scratch ----
__device__ float g_proj[PROJ_ROWS];
__device__ float g_yg[TV];
__device__ float g_x1[HID];
__device__ float g_act[INTER];

__device__ __forceinline__ float warp_sum(float v) {
#pragma unroll
    for (int o = 16; o; o >>= 1) v += __shfl_xor_sync(0xffffffffu, v, o);
    return v;
}

__device__ __forceinline__ void cp16(void* smem_dst, const void* gmem_src) {
    unsigned int sa = (unsigned int)__cvta_generic_to_shared(smem_dst);
    asm volatile("cp.async.cg.shared.global [%0], [%1], 16;" :: "r"(sa), "l"(gmem_src));
}
__device__ __forceinline__ void cp_commit() {
    asm volatile("cp.async.commit_group;");
}
__device__ __forceinline__ void cp_wait1() {
    asm volatile("cp.async.wait_group 1;");
}

// ================= pipelined GEMV =================
// Block = 256 threads. Stage = 16KB smem tile, double buffered, cp.async.cg.
// MODE_PLAIN / MODE_ATOMIC: tile = 2 chunk-rows of W (rows 2T, 2T+1 of this K-chunk).
// MODE_GATEUP: tile = {gate row T, up row T}; epilogue writes silu(g)*u.
// LN: stage sx = rmsnorm(xin) * (1+lnw); block(0,0) seeds xcopy = raw xin.
// Split-K via blockIdx.y: chunk base = blockIdx.y*KC into each W row (stride strideK)
// and into xin (when !LN).
template <int KC, int MODE, bool LN>
__global__ void __launch_bounds__(256)
gemv_pipe(const float* __restrict__ W, const float* __restrict__ W2,
          const float* __restrict__ xin, const float* __restrict__ lnw,
          float* __restrict__ outv, float* __restrict__ xcopy,
          int rows, int strideK) {
    __shared__ float sx[KC];
    __shared__ float4 buf[2][2][KC / 4];
    __shared__ float sacc[2][4];
    __shared__ float sred[9];
    const int tid = threadIdx.x;

    // ---- stage normalized/raw x into sx ----
    if (LN) {
        float s = 0.f;
        bool cp = (xcopy != nullptr) && (blockIdx.x == 0) && (blockIdx.y == 0);
        for (int i = tid; i < KC; i += 256) {
            float v = xin[i];
            sx[i] = v;
            if (cp) xcopy[i] = v;
            s += v * v;
        }
        s = warp_sum(s);
        if ((tid & 31) == 0) sred[tid >> 5] = s;
        __syncthreads();
        if (tid < 32) {
            float v = (tid < 8) ? sred[tid] : 0.f;
            v = warp_sum(v);
            if (tid == 0) sred[8] = rsqrtf(v / (float)KC + 1e-6f);
        }
        __syncthreads();
        float inv = sred[8];
        for (int i = tid; i < KC; i += 256)
            sx[i] = sx[i] * inv * (1.f + lnw[i]);
        __syncthreads();
    } else {
        const float* xc = xin + (size_t)blockIdx.y * KC;
        for (int i = tid; i < KC; i += 256) sx[i] = xc[i];
        __syncthreads();
    }

    const size_t cb = (size_t)blockIdx.y * KC;   // chunk base into W rows (floats)
    const int gx = gridDim.x;
    const int NT = (MODE == MODE_GATEUP) ? rows : (rows >> 1);

    auto issue = [&](int T, int b) {
        // 1024 16B units: unit u -> row_local (u>>9), float4 offset (u&511)
#pragma unroll
        for (int j = 0; j < 4; j++) {
            int u = j * 256 + tid;
            int rl = u >> 9;
            int off = u & 511;
            const float* g;
            if (MODE == MODE_GATEUP) {
                const float* Ws = rl ? W2 : W;
                g = Ws + (size_t)T * strideK + (size_t)off * 4;
            } else {
                int r = 2 * T + rl;
                g = W + (size_t)r * strideK + cb + (size_t)off * 4;
            }
            cp16(&buf[b][rl][off], g);
        }
    };

    // prologue: 2 tiles in flight
    int Ti = blockIdx.x;
#pragma unroll
    for (int d = 0; d < 2; d++) {
        if (Ti < NT) issue(Ti, d);
        cp_commit();
        Ti += gx;
    }

    const int w = tid >> 5, lane = tid & 31;
    const int rl = w >> 2, q = w & 3;
    const float4* xs4 = reinterpret_cast<const float4*>(sx);

    int b = 0;
    for (int Tc = blockIdx.x; Tc < NT; Tc += gx, b ^= 1) {
        cp_wait1();
        __syncthreads();
        // compute partials: warp (rl,q) covers quarter q of row rl
        {
            const float4* src = buf[b][rl];
            float acc = 0.f;
#pragma unroll
            for (int j = 0; j < KC / 512; j++) {
                int idx = q * (KC / 16) + j * 32 + lane;
                float4 wv = src[idx];
                float4 xv = xs4[idx];
                acc += wv.x * xv.x + wv.y * xv.y + wv.z * xv.z + wv.w * xv.w;
            }
            acc = warp_sum(acc);
            if (lane == 0) sacc[rl][q] = acc;
        }
        __syncthreads();
        // epilogue
        if (MODE == MODE_PLAIN) {
            if (tid < 2) {
                float s = sacc[tid][0] + sacc[tid][1] + sacc[tid][2] + sacc[tid][3];
                outv[2 * Tc + tid] = s;
            }
        } else if (MODE == MODE_ATOMIC) {
            if (tid < 2) {
                float s = sacc[tid][0] + sacc[tid][1] + sacc[tid][2] + sacc[tid][3];
                atomicAdd(&outv[2 * Tc + tid], s);
            }
        } else {
            if (tid == 0) {
                float ag = sacc[0][0] + sacc[0][1] + sacc[0][2] + sacc[0][3];
                float au = sacc[1][0] + sacc[1][1] + sacc[1][2] + sacc[1][3];
                float silu = ag / (1.f + expf(-ag));
                outv[Tc] = silu * au;
            }
        }
        // refill the buffer just consumed
        if (Ti < NT) issue(Ti, b);
        cp_commit();
        Ti += gx;
    }
}

// ================= gated delta rule with fused conv update =================
__global__ void __launch_bounds__(1024, 1)
delta_k(const float* __restrict__ S, const float* __restrict__ proj,
        const float* __restrict__ cs, const float* __restrict__ cw,
        const float* __restrict__ A_log, const float* __restrict__ dt_bias,
        const float* __restrict__ norm_w,
        float* __restrict__ Sout, float* __restrict__ out_cs, float* __restrict__ yg) {
    __shared__ float sq[KD], sk[KD], sv[VD], sdelta[VD], sred[8];
    __shared__ float spart[8][VD];
    int h = blockIdx.x;
    int tid = threadIdx.x;
    int t = tid & (VD - 1);
    int p = tid >> 7;
    int kh = h >> 1;

    if (tid < 384) {
        int row;
        if (tid < 128)      row = kh * KD + tid;
        else if (tid < 256) row = NKH * KD + kh * KD + (tid - 128);
        else                row = 2 * NKH * KD + h * VD + (tid - 256);
        float4 c = __ldg(reinterpret_cast<const float4*>(cs) + row);
        float4 w = __ldg(reinterpret_cast<const float4*>(cw) + row);
        float qv = proj[row];
        float s = c.y * w.x + c.z * w.y + c.w * w.z + qv * w.w;
        float act = s / (1.f + expf(-s));
        if (tid < 128)      sq[tid] = act;
        else if (tid < 256) sk[tid - 128] = act;
        else                sv[tid - 256] = act;
        if (tid >= 256 || (h & 1) == 0)
            reinterpret_cast<float4*>(out_cs)[row] = make_float4(c.y, c.z, c.w, qv);
    }
    __syncthreads();

    if (tid < 256) {
        float v = (tid < 128) ? sq[tid] : sk[tid - 128];
        float ss = warp_sum(v * v);
        if ((tid & 31) == 0) sred[tid >> 5] = ss;
    }
    __syncthreads();
    float sumq = sred[0] + sred[1] + sred[2] + sred[3];
    float sumk = sred[4] + sred[5] + sred[6] + sred[7];
    float inq = 1.f / fmaxf(sqrtf(sumq), 1e-12f);
    float ink = 1.f / fmaxf(sqrtf(sumk), 1e-12f);

    float a = proj[QKV + TV + h];
    float bb = proj[QKV + TV + NVH + h];
    float beta = 1.f / (1.f + expf(-bb));
    float xsp = a + dt_bias[h];
    float sp = (xsp > 20.f) ? xsp : log1pf(expf(xsp));
    float decay = expf(-expf(A_log[h]) * sp);

    const float* Sh = S + (size_t)h * KD * VD;
    float* So = Sout + (size_t)h * KD * VD;

    float Sreg[16];
    float acc = 0.f;
#pragma unroll
    for (int j = 0; j < 16; j++) {
        int k = p * 16 + j;
        Sreg[j] = Sh[k * VD + t];
        acc += Sreg[j] * sk[k];
    }
    spart[p][t] = acc * ink;
    __syncthreads();
    if (p == 0) {
        float s = 0.f;
#pragma unroll
        for (int j = 0; j < 8; j++) s += spart[j][t];
        sdelta[t] = sv[t] - s;
    }
    __syncthreads();

    float d = sdelta[t];
    float yacc = 0.f;
#pragma unroll
    for (int j = 0; j < 16; j++) {
        int k = p * 16 + j;
        float ns = decay * Sreg[j] + beta * (sk[k] * ink) * d;
        So[k * VD + t] = ns;
        yacc += ns * sq[k];
    }
    spart[p][t] = yacc * inq;
    __syncthreads();

    float y = 0.f;
    if (tid < VD) {
#pragma unroll
        for (int j = 0; j < 8; j++) y += spart[j][tid];
        float vy = warp_sum(y * y);
        if ((tid & 31) == 0) sred[tid >> 5] = vy;
    }
    __syncthreads();
    if (tid < VD) {
        float sumy = sred[0] + sred[1] + sred[2] + sred[3];
        float yn = y * rsqrtf(sumy / (float)VD + 1e-6f) * norm_w[tid];
        float z = proj[QKV + h * VD + tid];
        yg[h * VD + tid] = yn * (z / (1.f + expf(-z)));
    }
}

extern "C" void kernel_launch(void* const* d_in, const int* in_sizes, int n_in,
                              void* d_out, int out_size) {
    const float* x          = (const float*)d_in[0];
    const float* conv_state = (const float*)d_in[1];
    const float* ssm_state  = (const float*)d_in[2];
    const float* in_ln_w    = (const float*)d_in[3];
    const float* in_proj_w  = (const float*)d_in[4];
    const float* conv_w     = (const float*)d_in[5];
    const float* A_log      = (const float*)d_in[6];
    const float* dt_bias    = (const float*)d_in[7];
    const float* norm_w     = (const float*)d_in[8];
    const float* out_proj_w = (const float*)d_in[9];
    const float* post_ln_w  = (const float*)d_in[10];
    const float* gate_w     = (const float*)d_in[11];
    const float* up_w       = (const float*)d_in[12];
    const float* down_w     = (const float*)d_in[13];

    float* out = (float*)d_out;
    float* out_x    = out;
    float* out_conv = out + HID;
    float* out_ssm  = out + HID + QKV * 4;

    float *p_proj, *p_yg, *p_x1, *p_act;
    cudaGetSymbolAddress((void**)&p_proj, g_proj);
    cudaGetSymbolAddress((void**)&p_yg,   g_yg);
    cudaGetSymbolAddress((void**)&p_x1,   g_x1);
    cudaGetSymbolAddress((void**)&p_act,  g_act);

    // 1. in_proj (fused input rmsnorm; block0 seeds x1 = x): 12352 x 2048
    gemv_pipe<HID, MODE_PLAIN, true><<<640, 256>>>(
        in_proj_w, nullptr, x, in_ln_w, p_proj, p_x1, PROJ_ROWS, HID);
    // 2. gated delta rule + fused conv; writes new_conv_state and new_ssm_state
    delta_k<<<NVH, 1024>>>(ssm_state, p_proj, conv_state, conv_w,
                           A_log, dt_bias, norm_w, out_ssm, out_conv, p_yg);
    // 3. out_proj split-2, accumulates onto x1: 2048 x 4096
    gemv_pipe<HID, MODE_ATOMIC, false><<<dim3(320, 2), 256>>>(
        out_proj_w, nullptr, p_yg, nullptr, p_x1, nullptr, HID, TV);
    // 4. fused post-rmsnorm + gate/up + SwiGLU; block0 seeds out_x = x1
    gemv_pipe<HID, MODE_GATEUP, true><<<640, 256>>>(
        gate_w, up_w, p_x1, post_ln_w, p_act, out_x, INTER, HID);
    // 5. down split-4, accumulates onto out_x: 2048 x 8192
    gemv_pipe<HID, MODE_ATOMIC, false><<<dim3(160, 4), 256>>>(
        down_w, nullptr, p_act, nullptr, out_x, nullptr, HID, INTER);
}